// round 7
// baseline (speedup 1.0000x reference)
#include <cuda_runtime.h>
#include <cuda_fp16.h>
#include <cstdint>
#include <cstddef>

#define DMODEL 1024
#define FDIM   4096
#define NEXP   8
#define NMAX   4096
#define BK     64          // 64 fp16 = 128B = one swizzle row

#define BM 128
#define BN 64

// ---------------- device scratch (static only) ----------------
__device__ __half d_Hh[(size_t)NMAX * FDIM];     // 32 MB fp16 intermediate
__device__ __half d_xh[(size_t)NMAX * DMODEL];   // 8 MB fp16 activations
__device__ int   d_idx[NMAX];
__device__ float d_prob[NMAX];
__device__ int   d_counts[NEXP];
__device__ float d_imp[NEXP];
__device__ int   d_offsets[NEXP + 1];
__device__ int   d_cursor[NEXP];
__device__ int   d_perm[NMAX];

// ---------------- helpers ----------------
__device__ __forceinline__ uint32_t smem_u32(const void* p) {
    return (uint32_t)__cvta_generic_to_shared(p);
}
__device__ __forceinline__ void cpa16(uint32_t s, const __half* g) {
    asm volatile("cp.async.cg.shared.global [%0], [%1], 16;" :: "r"(s), "l"(g));
}
__device__ __forceinline__ void cp_commit() { asm volatile("cp.async.commit_group;"); }
__device__ __forceinline__ void cp_wait0()  { asm volatile("cp.async.wait_group 0;" ::: "memory"); }

__device__ __forceinline__ void ldmx4(uint32_t* r, uint32_t a) {
    asm volatile("ldmatrix.sync.aligned.m8n8.x4.shared.b16 {%0,%1,%2,%3}, [%4];"
                 : "=r"(r[0]), "=r"(r[1]), "=r"(r[2]), "=r"(r[3]) : "r"(a));
}
// D += A(16x16) * B(16x8), fp16 in, f32 accum
__device__ __forceinline__ void mma16(float* c, const uint32_t* a, uint32_t b0, uint32_t b1) {
    asm volatile(
        "mma.sync.aligned.m16n8k16.row.col.f32.f16.f16.f32 "
        "{%0,%1,%2,%3},{%4,%5,%6,%7},{%8,%9},{%0,%1,%2,%3};"
        : "+f"(c[0]), "+f"(c[1]), "+f"(c[2]), "+f"(c[3])
        : "r"(a[0]), "r"(a[1]), "r"(a[2]), "r"(a[3]), "r"(b0), "r"(b1));
}

// swizzled byte offset inside a tile: row * 128B + xor'd 16B unit
__device__ __forceinline__ uint32_t swz(int row, int unit) {
    return (uint32_t)(row * 128 + ((unit ^ (row & 7)) << 4));
}
__device__ __forceinline__ uint32_t pk2(float x, float y) {
    __half2 h = __floats2half2_rn(x, y);
    return *(uint32_t*)&h;
}
__device__ __forceinline__ uint4 pack8(float4 a, float4 b) {
    uint4 t;
    t.x = pk2(a.x, a.y); t.y = pk2(a.z, a.w);
    t.z = pk2(b.x, b.y); t.w = pk2(b.z, b.w);
    return t;
}

// ---------------- prep: f32 -> fp16 (x only) ----------------
__global__ void cvt_kernel(const float* __restrict__ s, __half* __restrict__ d, int n4) {
    int stride = gridDim.x * blockDim.x;
    for (int i = blockIdx.x * blockDim.x + threadIdx.x; i < n4; i += stride) {
        float4 v = ((const float4*)s)[i];
        ((__half2*)d)[2 * i]     = __floats2half2_rn(v.x, v.y);
        ((__half2*)d)[2 * i + 1] = __floats2half2_rn(v.z, v.w);
    }
}

// ---------------- gating / routing ----------------
__global__ void init_kernel() {
    int t = threadIdx.x;
    if (t < NEXP) { d_counts[t] = 0; d_imp[t] = 0.f; }
}

__global__ void gating_kernel(const float* __restrict__ x,
                              const float* __restrict__ gw, int N) {
    __shared__ float sgw[NEXP * DMODEL];
    __shared__ float s_imp[NEXP];
    __shared__ int   s_cnt[NEXP];
    int tid = threadIdx.x;
    for (int i = tid; i < NEXP * DMODEL; i += blockDim.x) sgw[i] = gw[i];
    if (tid < NEXP) { s_imp[tid] = 0.f; s_cnt[tid] = 0; }
    __syncthreads();

    int warp = tid >> 5, lane = tid & 31;
    int n = blockIdx.x * 8 + warp;
    if (n < N) {
        float acc[NEXP];
        #pragma unroll
        for (int e = 0; e < NEXP; e++) acc[e] = 0.f;
        const float* xr = x + (size_t)n * DMODEL;
        for (int i = lane; i < DMODEL; i += 32) {
            float xv = xr[i];
            #pragma unroll
            for (int e = 0; e < NEXP; e++) acc[e] += xv * sgw[e * DMODEL + i];
        }
        #pragma unroll
        for (int e = 0; e < NEXP; e++) {
            #pragma unroll
            for (int o = 16; o > 0; o >>= 1)
                acc[e] += __shfl_down_sync(0xffffffffu, acc[e], o);
        }
        if (lane == 0) {
            float m = acc[0]; int am = 0;
            #pragma unroll
            for (int e = 1; e < NEXP; e++) if (acc[e] > m) { m = acc[e]; am = e; }
            float p[NEXP]; float s = 0.f;
            #pragma unroll
            for (int e = 0; e < NEXP; e++) { p[e] = expf(acc[e] - m); s += p[e]; }
            float inv = 1.f / s;
            #pragma unroll
            for (int e = 0; e < NEXP; e++) atomicAdd(&s_imp[e], p[e] * inv);
            d_idx[n]  = am;
            d_prob[n] = p[am] * inv;
            atomicAdd(&s_cnt[am], 1);
        }
    }
    __syncthreads();
    if (tid < NEXP) {
        atomicAdd(&d_imp[tid],    s_imp[tid]);
        atomicAdd(&d_counts[tid], s_cnt[tid]);
    }
}

__global__ void offsets_kernel(int N, float* aux_out) {
    if (threadIdx.x == 0) {
        int off = 0;
        #pragma unroll
        for (int e = 0; e < NEXP; e++) {
            d_offsets[e] = off; off += d_counts[e]; d_cursor[e] = 0;
        }
        d_offsets[NEXP] = off;
        if (aux_out) {
            float invN = 1.f / (float)N;
            float aux = 0.f;
            #pragma unroll
            for (int e = 0; e < NEXP; e++)
                aux += ((float)d_counts[e] * invN) * (d_imp[e] * invN);
            *aux_out = aux * (float)NEXP * 0.01f;
        }
    }
}

__global__ void scatter_kernel(int N) {
    int n = blockIdx.x * blockDim.x + threadIdx.x;
    if (n < N) {
        int e = d_idx[n];
        int pos = d_offsets[e] + atomicAdd(&d_cursor[e], 1);
        d_perm[pos] = n;
    }
}

// ================ GEMM1: H = silu(X W1^T) * (X W3^T), fp16 mma ================
// smem bytes: rows[128] @0, A @1024 (2x16KB fp16), B1 @33792 (2x8KB), B3 @50176 (2x8KB)
#define G1_SMEM 66560

__global__ __launch_bounds__(256, 1)
void gemm1_kernel(const float* __restrict__ w1, const float* __restrict__ w3) {
    int e   = blockIdx.z;
    int off = d_offsets[e];
    int cnt = d_offsets[e + 1] - off;
    int m0  = blockIdx.y * BM;
    if (m0 >= cnt) return;
    int n0 = blockIdx.x * BN;

    extern __shared__ char smem[];
    int* rows = (int*)smem;
    uint32_t sb  = smem_u32(smem);
    uint32_t sbA = sb + 1024;
    char* B1p = smem + 33792;
    char* B3p = smem + 50176;

    int tid = threadIdx.x, wid = tid >> 5, lane = tid & 31;
    int wm = wid >> 1, wn = wid & 1;          // 4(m) x 2(n) warps; warp tile 32x32

    for (int i = tid; i < BM; i += 256) {
        int mi = m0 + i;
        rows[i] = d_perm[off + (mi < cnt ? mi : 0)];
    }
    __syncthreads();

    // B-row/unit handled by this thread (2 (row,unit) pairs)
    int br[2], bu[2];
    #pragma unroll
    for (int p = 0; p < 2; p++) { int idx = p * 256 + tid; br[p] = idx >> 3; bu[p] = idx & 7; }

    float4 b1v[2][2], b3v[2][2];
    auto loadB = [&](int it) {
        int kk = it * BK;
        #pragma unroll
        for (int p = 0; p < 2; p++) {
            const float* g1 = w1 + ((size_t)e * FDIM + n0 + br[p]) * DMODEL + kk + bu[p] * 8;
            const float* g3 = w3 + ((size_t)e * FDIM + n0 + br[p]) * DMODEL + kk + bu[p] * 8;
            b1v[p][0] = __ldg((const float4*)g1);
            b1v[p][1] = __ldg((const float4*)(g1 + 4));
            b3v[p][0] = __ldg((const float4*)g3);
            b3v[p][1] = __ldg((const float4*)(g3 + 4));
        }
    };
    auto stsB = [&](int buf) {
        #pragma unroll
        for (int p = 0; p < 2; p++) {
            uint32_t so = swz(br[p], bu[p]);
            *(uint4*)(B1p + buf * 8192 + so) = pack8(b1v[p][0], b1v[p][1]);
            *(uint4*)(B3p + buf * 8192 + so) = pack8(b3v[p][0], b3v[p][1]);
        }
    };
    auto fillA = [&](int it, int buf) {
        int kk = it * BK;
        uint32_t Ab = sbA + buf * 16384;
        #pragma unroll
        for (int p = 0; p < 4; p++) {
            int idx = p * 256 + tid;
            int r = idx >> 3, u = idx & 7;
            cpa16(Ab + swz(r, u), d_xh + (size_t)rows[r] * DMODEL + kk + u * 8);
        }
        cp_commit();
    };

    // ldmatrix lane-partition constants
    int pa_r = ((lane >> 3) & 1) * 8 + (lane & 7);
    int pa_u = lane >> 4;
    int pb_r = ((lane >> 4) << 3) + (lane & 7);
    int pb_u = (lane >> 3) & 1;
    int rowA[2], rowB[2];
    #pragma unroll
    for (int mt = 0; mt < 2; mt++) rowA[mt] = wm * 32 + mt * 16 + pa_r;
    #pragma unroll
    for (int np = 0; np < 2; np++) rowB[np] = wn * 32 + np * 16 + pb_r;

    float uacc[2][4][4], vacc[2][4][4];
    #pragma unroll
    for (int a = 0; a < 2; a++)
        #pragma unroll
        for (int b = 0; b < 4; b++)
            #pragma unroll
            for (int q = 0; q < 4; q++) { uacc[a][b][q] = 0.f; vacc[a][b][q] = 0.f; }

    // pipeline prologue
    loadB(0);
    fillA(0, 0);
    stsB(0);
    loadB(1);
    cp_wait0();
    __syncthreads();

    const int NIT = DMODEL / BK;   // 16
    uint32_t sbB1 = sb + 33792, sbB3 = sb + 50176;
    for (int it = 0; it < NIT; it++) {
        int buf = it & 1;
        if (it + 1 < NIT) {
            fillA(it + 1, buf ^ 1);
            stsB(buf ^ 1);
            if (it + 2 < NIT) loadB(it + 2);
        }

        uint32_t Ab = sbA + buf * 16384, B1b = sbB1 + buf * 8192, B3b = sbB3 + buf * 8192;
        #pragma unroll
        for (int ks = 0; ks < 4; ks++) {
            uint32_t a[2][4];
            #pragma unroll
            for (int mt = 0; mt < 2; mt++)
                ldmx4(a[mt], Ab + swz(rowA[mt], ks * 2 + pa_u));
            #pragma unroll
            for (int np = 0; np < 2; np++) {
                uint32_t b1[4], b3[4];
                uint32_t so = swz(rowB[np], ks * 2 + pb_u);
                ldmx4(b1, B1b + so);
                ldmx4(b3, B3b + so);
                #pragma unroll
                for (int h = 0; h < 2; h++)
                    #pragma unroll
                    for (int mt = 0; mt < 2; mt++) {
                        mma16(uacc[mt][np * 2 + h], a[mt], b1[h * 2], b1[h * 2 + 1]);
                        mma16(vacc[mt][np * 2 + h], a[mt], b3[h * 2], b3[h * 2 + 1]);
                    }
            }
        }
        if (it + 1 < NIT) { cp_wait0(); __syncthreads(); }
    }

    // epilogue: silu(u)*v -> fp16 H
    int g = lane >> 2, c2 = (lane & 3) * 2;
    #pragma unroll
    for (int mt = 0; mt < 2; mt++) {
        #pragma unroll
        for (int i = 0; i < 2; i++) {
            int r = m0 + wm * 32 + mt * 16 + g + i * 8;
            if (r < cnt) {
                __half* hp = d_Hh + (size_t)(off + r) * FDIM + n0 + wn * 32;
                #pragma unroll
                for (int nt = 0; nt < 4; nt++) {
                    float u0 = uacc[mt][nt][i * 2], u1 = uacc[mt][nt][i * 2 + 1];
                    float v0 = vacc[mt][nt][i * 2], v1 = vacc[mt][nt][i * 2 + 1];
                    float h0 = u0 / (1.f + __expf(-u0)) * v0;
                    float h1 = u1 / (1.f + __expf(-u1)) * v1;
                    *(__half2*)(hp + nt * 8 + c2) = __floats2half2_rn(h0, h1);
                }
            }
        }
    }
}

// ================ GEMM2: out = (H @ W2^T) * prob, fp16 mma ================
// smem bytes: A @0 (2x16KB), B @32768 (2x8KB)
#define G2_SMEM 49152

__global__ __launch_bounds__(256, 2)
void gemm2_kernel(const float* __restrict__ w2, float* __restrict__ out) {
    int e   = blockIdx.z;
    int off = d_offsets[e];
    int cnt = d_offsets[e + 1] - off;
    int m0  = blockIdx.y * BM;
    if (m0 >= cnt) return;
    int n0 = blockIdx.x * BN;

    extern __shared__ char smem[];
    uint32_t sb  = smem_u32(smem);
    uint32_t sbA = sb, sbB = sb + 32768;
    char* Bp = smem + 32768;

    int tid = threadIdx.x, wid = tid >> 5, lane = tid & 31;
    int wm = wid >> 1, wn = wid & 1;

    int br[2], bu[2];
    #pragma unroll
    for (int p = 0; p < 2; p++) { int idx = p * 256 + tid; br[p] = idx >> 3; bu[p] = idx & 7; }

    float4 bv[2][2];
    auto loadB = [&](int it) {
        int kk = it * BK;
        #pragma unroll
        for (int p = 0; p < 2; p++) {
            const float* gb = w2 + ((size_t)e * DMODEL + n0 + br[p]) * FDIM + kk + bu[p] * 8;
            bv[p][0] = __ldg((const float4*)gb);
            bv[p][1] = __ldg((const float4*)(gb + 4));
        }
    };
    auto stsB = [&](int buf) {
        #pragma unroll
        for (int p = 0; p < 2; p++)
            *(uint4*)(Bp + buf * 8192 + swz(br[p], bu[p])) = pack8(bv[p][0], bv[p][1]);
    };
    auto fillA = [&](int it, int buf) {
        int kk = it * BK;
        uint32_t Ab = sbA + buf * 16384;
        #pragma unroll
        for (int p = 0; p < 4; p++) {
            int idx = p * 256 + tid;
            int r = idx >> 3, u = idx & 7;
            int mi = m0 + r; if (mi >= cnt) mi = cnt - 1;
            cpa16(Ab + swz(r, u), d_Hh + (size_t)(off + mi) * FDIM + kk + u * 8);
        }
        cp_commit();
    };

    int pa_r = ((lane >> 3) & 1) * 8 + (lane & 7);
    int pa_u = lane >> 4;
    int pb_r = ((lane >> 4) << 3) + (lane & 7);
    int pb_u = (lane >> 3) & 1;
    int rowA[2], rowB[2];
    #pragma unroll
    for (int mt = 0; mt < 2; mt++) rowA[mt] = wm * 32 + mt * 16 + pa_r;
    #pragma unroll
    for (int np = 0; np < 2; np++) rowB[np] = wn * 32 + np * 16 + pb_r;

    float acc[2][4][4];
    #pragma unroll
    for (int a = 0; a < 2; a++)
        #pragma unroll
        for (int b = 0; b < 4; b++)
            #pragma unroll
            for (int q = 0; q < 4; q++) acc[a][b][q] = 0.f;

    loadB(0);
    fillA(0, 0);
    stsB(0);
    loadB(1);
    cp_wait0();
    __syncthreads();

    const int NIT = FDIM / BK;   // 64
    for (int it = 0; it < NIT; it++) {
        int buf = it & 1;
        if (it + 1 < NIT) {
            fillA(it + 1, buf ^ 1);
            stsB(buf ^ 1);
            if (it + 2 < NIT) loadB(it + 2);
        }

        uint32_t Ab = sbA + buf * 16384, Bb = sbB + buf * 8192;
        #pragma unroll
        for (int ks = 0; ks < 4; ks++) {
            uint32_t a[2][4];
            #pragma unroll
            for (int mt = 0; mt < 2; mt++)
                ldmx4(a[mt], Ab + swz(rowA[mt], ks * 2 + pa_u));
            #pragma unroll
            for (int np = 0; np < 2; np++) {
                uint32_t b[4];
                ldmx4(b, Bb + swz(rowB[np], ks * 2 + pb_u));
                #pragma unroll
                for (int h = 0; h < 2; h++)
                    #pragma unroll
                    for (int mt = 0; mt < 2; mt++)
                        mma16(acc[mt][np * 2 + h], a[mt], b[h * 2], b[h * 2 + 1]);
            }
        }
        if (it + 1 < NIT) { cp_wait0(); __syncthreads(); }
    }

    int g = lane >> 2, c2 = (lane & 3) * 2;
    #pragma unroll
    for (int mt = 0; mt < 2; mt++) {
        #pragma unroll
        for (int i = 0; i < 2; i++) {
            int r = m0 + wm * 32 + mt * 16 + g + i * 8;
            if (r < cnt) {
                int token = d_perm[off + r];
                float ps  = d_prob[token];
                float* op = out + (size_t)token * DMODEL + n0 + wn * 32;
                #pragma unroll
                for (int nt = 0; nt < 4; nt++) {
                    float2 o;
                    o.x = acc[mt][nt][i * 2]     * ps;
                    o.y = acc[mt][nt][i * 2 + 1] * ps;
                    *(float2*)(op + nt * 8 + c2) = o;
                }
            }
        }
    }
}

// ---------------- launch ----------------
extern "C" void kernel_launch(void* const* d_in, const int* in_sizes, int n_in,
                              void* d_out, int out_size) {
    const float* x  = (const float*)d_in[0];
    const float* gw = (const float*)d_in[1];
    const float* w1 = (const float*)d_in[2];
    const float* w2 = (const float*)d_in[3];
    const float* w3 = (const float*)d_in[4];
    float* out = (float*)d_out;

    int N = in_sizes[0] / DMODEL;   // 4096
    if (N > NMAX) N = NMAX;

    cudaFuncSetAttribute(gemm1_kernel, cudaFuncAttributeMaxDynamicSharedMemorySize, G1_SMEM);
    cudaFuncSetAttribute(gemm2_kernel, cudaFuncAttributeMaxDynamicSharedMemorySize, G2_SMEM);

    float* aux_out = (out_size > N * DMODEL) ? (out + (size_t)N * DMODEL) : nullptr;

    __half* xh;
    cudaGetSymbolAddress((void**)&xh, d_xh);

    // f32 -> fp16 prep for activations only (weights converted in-GEMM)
    cvt_kernel<<<296, 256>>>(x, xh, N * DMODEL / 4);

    init_kernel<<<1, 32>>>();
    gating_kernel<<<(N + 7) / 8, 256>>>(x, gw, N);
    offsets_kernel<<<1, 32>>>(N, aux_out);
    scatter_kernel<<<(N + 255) / 256, 256>>>(N);

    int mtiles = (N + BM - 1) / BM;            // 32 worst-case
    dim3 g1(FDIM / BN, mtiles, NEXP);          // (64, 32, 8)
    gemm1_kernel<<<g1, 256, G1_SMEM>>>(w1, w3);

    dim3 g2(DMODEL / BN, mtiles, NEXP);        // (16, 32, 8)
    gemm2_kernel<<<g2, 256, G2_SMEM>>>(w2, out);
}